// round 10
// baseline (speedup 1.0000x reference)
#include <cuda_runtime.h>
#include <cuda_fp16.h>
#include <math.h>

#define CV 10000
#define CE 512
#define CH 1024
#define CK 2048
#define CB 64
#define CS 196
#define CT 15
#define NB 128   // mega-kernel grid size (must be <= resident capacity)

// ---------------- scratch layout (float units, 16B-aligned) ----------------
#define OFF_XEMB    0u
#define OFF_XSEQT   491520u
#define OFF_GIX     1474560u
#define OFF_KEYS16  4423680u
#define OFF_FEAT16  10846208u
#define OFF_WQ16    23691264u
#define OFF_FC016   24215552u
#define OFF_FC216   25264128u
#define OFF_WI0C    30384128u
#define OFF_WH016   31956992u
#define OFF_WIL16   33529856u
#define OFF_WHL16   38248448u
#define OFF_E       42967040u
#define OFF_QP      42992128u
#define OFF_QS      43516416u
#define OFF_CTX16   43581952u
#define OFF_CTXH16  43647488u
#define OFF_H32A    43680256u
#define OFF_H32B    43942400u
#define OFF_H16A    44204544u
#define OFF_H16B    44335616u
#define OFF_FC0P    44466688u
#define OFF_HALL    44990976u
#define SCRATCH_TOTAL 45482496u

__device__ __align__(16) float g_scratch[SCRATCH_TOTAL];

// ---- grid barrier state ----
__device__ unsigned g_cnt = 0;
__device__ volatile unsigned g_gen = 0;

__device__ __forceinline__ void gbar() {
    __threadfence();
    __syncthreads();
    if (threadIdx.x == 0) {
        unsigned g = g_gen;
        if (atomicAdd(&g_cnt, 1u) == NB - 1u) {
            g_cnt = 0u;
            __threadfence();
            g_gen = g + 1u;
        } else {
            while (g_gen == g) __nanosleep(32);
        }
        __threadfence();
    }
    __syncthreads();
}

__device__ __forceinline__ float fast_tanh(float x) {
    float e = __expf(2.0f * x);
    return 1.0f - __fdividef(2.0f, 1.0f + e);
}

__device__ __forceinline__ float tf32r(float x) {
    unsigned u;
    asm("cvt.rna.tf32.f32 %0, %1;" : "=r"(u) : "f"(x));
    return __uint_as_float(u);
}

__device__ __forceinline__ void mma8(float* c, const unsigned* a, const unsigned* b) {
    asm volatile(
        "mma.sync.aligned.m16n8k8.row.col.f32.tf32.tf32.f32 "
        "{%0,%1,%2,%3}, {%4,%5,%6,%7}, {%8,%9}, {%0,%1,%2,%3};\n"
        : "+f"(c[0]), "+f"(c[1]), "+f"(c[2]), "+f"(c[3])
        : "r"(a[0]), "r"(a[1]), "r"(a[2]), "r"(a[3]), "r"(b[0]), "r"(b[1]));
}

__device__ __forceinline__ void mma16(float* c, const unsigned* a, const unsigned* b) {
    asm volatile(
        "mma.sync.aligned.m16n8k16.row.col.f32.f16.f16.f32 "
        "{%0,%1,%2,%3}, {%4,%5,%6,%7}, {%8,%9}, {%0,%1,%2,%3};\n"
        : "+f"(c[0]), "+f"(c[1]), "+f"(c[2]), "+f"(c[3])
        : "r"(a[0]), "r"(a[1]), "r"(a[2]), "r"(a[3]), "r"(b[0]), "r"(b[1]));
}

// ---------------- tf32 GEMM (prologue; proven) ----------------
template<bool STORE_T, bool HOUT>
__global__ void __launch_bounds__(256)
gemm_tf32(const float* __restrict__ A, const float* __restrict__ B,
          const float* __restrict__ bias, float* __restrict__ C,
          int M, int K, int lda, int ldb, int ldc, size_t zstride)
{
    __shared__ float As[128 * 44];
    __shared__ float Bs[32 * 72];
    int tid = threadIdx.x;
    int lane = tid & 31, w = tid >> 5;
    int wm = (w & 3) * 32, wn = (w >> 2) * 32;
    int bn = blockIdx.x * 64, bm = blockIdx.y * 128;
    int kper = K / gridDim.z;
    int k0 = blockIdx.z * kper, kend = k0 + kper;
    C += (size_t)blockIdx.z * zstride;

    float acc[2][4][4] = {};
    float4 apf[4], bpf[2];
    {
        int kc = k0;
#pragma unroll
        for (int i = 0; i < 4; i++) {
            int f = tid + i * 256, m = f >> 3, k4 = f & 7;
            int gm = bm + m; if (gm >= M) gm = M - 1;
            apf[i] = *(const float4*)(A + (size_t)gm * lda + kc + k4 * 4);
        }
#pragma unroll
        for (int i = 0; i < 2; i++) {
            int f = tid + i * 256, kr = f >> 4, n4 = f & 15;
            bpf[i] = *(const float4*)(B + (size_t)(kc + kr) * ldb + bn + n4 * 4);
        }
    }
    for (int kc = k0; kc < kend; kc += 32) {
#pragma unroll
        for (int i = 0; i < 4; i++) {
            int f = tid + i * 256, m = f >> 3, k4 = f & 7;
            float4 v = apf[i];
            *(float4*)&As[m * 44 + k4 * 4] =
                make_float4(tf32r(v.x), tf32r(v.y), tf32r(v.z), tf32r(v.w));
        }
#pragma unroll
        for (int i = 0; i < 2; i++) {
            int f = tid + i * 256, kr = f >> 4, n4 = f & 15;
            float4 v = bpf[i];
            *(float4*)&Bs[kr * 72 + n4 * 4] =
                make_float4(tf32r(v.x), tf32r(v.y), tf32r(v.z), tf32r(v.w));
        }
        __syncthreads();
        if (kc + 32 < kend) {
            int kn = kc + 32;
#pragma unroll
            for (int i = 0; i < 4; i++) {
                int f = tid + i * 256, m = f >> 3, k4 = f & 7;
                int gm = bm + m; if (gm >= M) gm = M - 1;
                apf[i] = *(const float4*)(A + (size_t)gm * lda + kn + k4 * 4);
            }
#pragma unroll
            for (int i = 0; i < 2; i++) {
                int f = tid + i * 256, kr = f >> 4, n4 = f & 15;
                bpf[i] = *(const float4*)(B + (size_t)(kn + kr) * ldb + bn + n4 * 4);
            }
        }
        const unsigned* Asu = (const unsigned*)As;
        const unsigned* Bsu = (const unsigned*)Bs;
        int r = lane >> 2, cq = lane & 3;
#pragma unroll
        for (int kk = 0; kk < 4; kk++) {
            unsigned a[2][4], bf[4][2];
#pragma unroll
            for (int t = 0; t < 2; t++) {
                int base = (wm + t * 16 + r) * 44 + kk * 8 + cq;
                a[t][0] = Asu[base]; a[t][1] = Asu[base + 8 * 44];
                a[t][2] = Asu[base + 4]; a[t][3] = Asu[base + 8 * 44 + 4];
            }
#pragma unroll
            for (int j = 0; j < 4; j++) {
                int base = (kk * 8 + cq) * 72 + wn + j * 8 + r;
                bf[j][0] = Bsu[base]; bf[j][1] = Bsu[base + 4 * 72];
            }
#pragma unroll
            for (int t = 0; t < 2; t++)
#pragma unroll
                for (int j = 0; j < 4; j++)
                    mma8(acc[t][j], a[t], bf[j]);
        }
        __syncthreads();
    }
    int r = lane >> 2, cq = lane & 3;
#pragma unroll
    for (int t = 0; t < 2; t++) {
#pragma unroll
        for (int j = 0; j < 4; j++) {
            int row0 = bm + wm + t * 16 + r;
            int col = bn + wn + j * 8 + cq * 2;
            float* ac = acc[t][j];
            float b0 = bias ? bias[col] : 0.0f;
            float b1 = bias ? bias[col + 1] : 0.0f;
            if (STORE_T) {
                if (row0 < M) {
                    C[(size_t)col * ldc + row0] = ac[0] + b0;
                    C[(size_t)(col + 1) * ldc + row0] = ac[1] + b1;
                }
                if (row0 + 8 < M) {
                    C[(size_t)col * ldc + row0 + 8] = ac[2] + b0;
                    C[(size_t)(col + 1) * ldc + row0 + 8] = ac[3] + b1;
                }
            } else if (HOUT) {
                __half* Ch = (__half*)C;
                if (row0 < M)
                    *(__half2*)(Ch + (size_t)row0 * ldc + col) = __floats2half2_rn(ac[0] + b0, ac[1] + b1);
                if (row0 + 8 < M)
                    *(__half2*)(Ch + (size_t)(row0 + 8) * ldc + col) = __floats2half2_rn(ac[2] + b0, ac[3] + b1);
            } else {
                if (row0 < M)
                    *(float2*)(C + (size_t)row0 * ldc + col) = make_float2(ac[0] + b0, ac[1] + b1);
                if (row0 + 8 < M)
                    *(float2*)(C + (size_t)(row0 + 8) * ldc + col) = make_float2(ac[2] + b0, ac[3] + b1);
            }
        }
    }
}

// ---------------- device fp16 GEMM tile (one 128-row tile, one K-chunk) -----
template<bool STORE_T>
__device__ __forceinline__ void dev_gemm_h(
    const __half* __restrict__ A, const __half* __restrict__ B,
    float* __restrict__ C, int M, int lda, int ldb, int ldc,
    int bm, int k0, int klen, char* pool)
{
    __half* As = (__half*)pool;             // 128*40 halves
    __half* Bs = (__half*)(pool + 10240);   // 64*40 halves
    int tid = threadIdx.x;
    int lane = tid & 31, w = tid >> 5;
    int wm = (w & 3) * 32, wn = (w >> 2) * 32;
    int kend = k0 + klen;

    float acc[2][4][4] = {};
    uint4 apf[2], bpf;
    {
#pragma unroll
        for (int i = 0; i < 2; i++) {
            int f = tid + i * 256, row = f >> 2, v = f & 3;
            int gm = bm + row; if (gm >= M) gm = M - 1;
            apf[i] = *(const uint4*)(A + (size_t)gm * lda + k0 + v * 8);
        }
        { int n = tid >> 2, v = tid & 3;
          bpf = *(const uint4*)(B + (size_t)n * ldb + k0 + v * 8); }
    }
    for (int kc = k0; kc < kend; kc += 32) {
#pragma unroll
        for (int i = 0; i < 2; i++) {
            int f = tid + i * 256, row = f >> 2, v = f & 3;
            *(uint4*)&As[row * 40 + v * 8] = apf[i];
        }
        { int n = tid >> 2, v = tid & 3;
          *(uint4*)&Bs[n * 40 + v * 8] = bpf; }
        __syncthreads();
        if (kc + 32 < kend) {
            int kn = kc + 32;
#pragma unroll
            for (int i = 0; i < 2; i++) {
                int f = tid + i * 256, row = f >> 2, v = f & 3;
                int gm = bm + row; if (gm >= M) gm = M - 1;
                apf[i] = *(const uint4*)(A + (size_t)gm * lda + kn + v * 8);
            }
            { int n = tid >> 2, v = tid & 3;
              bpf = *(const uint4*)(B + (size_t)n * ldb + kn + v * 8); }
        }
        const unsigned* Au = (const unsigned*)As;
        const unsigned* Bu = (const unsigned*)Bs;
        int r = lane >> 2, cq = lane & 3;
#pragma unroll
        for (int kk = 0; kk < 2; kk++) {
            unsigned a[2][4], bf[4][2];
#pragma unroll
            for (int t = 0; t < 2; t++) {
                int base = (wm + t * 16 + r) * 20 + kk * 8 + cq;
                a[t][0] = Au[base]; a[t][1] = Au[base + 160];
                a[t][2] = Au[base + 4]; a[t][3] = Au[base + 164];
            }
#pragma unroll
            for (int j = 0; j < 4; j++) {
                int base = (wn + j * 8 + r) * 20 + kk * 8 + cq;
                bf[j][0] = Bu[base]; bf[j][1] = Bu[base + 4];
            }
#pragma unroll
            for (int t = 0; t < 2; t++)
#pragma unroll
                for (int j = 0; j < 4; j++)
                    mma16(acc[t][j], a[t], bf[j]);
        }
        __syncthreads();
    }
    int r = lane >> 2, cq = lane & 3;
#pragma unroll
    for (int t = 0; t < 2; t++) {
#pragma unroll
        for (int j = 0; j < 4; j++) {
            int row0 = bm + wm + t * 16 + r;
            int col = wn + j * 8 + cq * 2;
            float* ac = acc[t][j];
            if (STORE_T) {
                if (row0 < M) {
                    C[(size_t)col * ldc + row0] = ac[0];
                    C[(size_t)(col + 1) * ldc + row0] = ac[1];
                }
                if (row0 + 8 < M) {
                    C[(size_t)col * ldc + row0 + 8] = ac[2];
                    C[(size_t)(col + 1) * ldc + row0 + 8] = ac[3];
                }
            } else {
                if (row0 < M)
                    *(float2*)(C + (size_t)row0 * ldc + col) = make_float2(ac[0], ac[1]);
                if (row0 + 8 < M)
                    *(float2*)(C + (size_t)(row0 + 8) * ldc + col) = make_float2(ac[2], ac[3]);
            }
        }
    }
}

// ---------------- device fused GRU layer (one 16-j chunk) --------------------
__device__ __forceinline__ void dev_gru(
    int J0,
    const __half* __restrict__ Wi, const __half* __restrict__ Wh,
    const __half* __restrict__ x16, const __half* __restrict__ hin16,
    const float* __restrict__ hin32, float* __restrict__ hout32,
    __half* __restrict__ hout16, const float* __restrict__ gix,
    const float* __restrict__ bi, const float* __restrict__ bh,
    char* poolc)
{
    float* pool = (float*)poolc;
    __half* As = (__half*)pool;
    __half* Bs = (__half*)(pool + 3456);
    float* gi_s = pool;
    float* gh_s = pool + 3120;

    int tid = threadIdx.x;
    int lane = tid & 31, w = tid >> 5;
    int g = (w >> 1) & 3, nh = w & 1;   // warps 0..5 used; 6,7 idle in mma
    bool active = (w < 6);
    int r = lane >> 2, cq = lane & 3;

    float accI[4][4] = {}, accH[4][4] = {};
    uint4 pf[7];   // 256 threads * 7 >= 1792

#pragma unroll
    for (int i = 0; i < 7; i++) {
        int f = tid + i * 256;
        if (f < 768) {
            int mat = f >= 384; int ff = f - mat * 384;
            int row = ff >> 3, v = ff & 7;
            int grow = ((row >> 4) << 10) + J0 + (row & 15);
            pf[i] = *(const uint4*)((mat ? Wh : Wi) + (size_t)grow * 1024 + v * 8);
        } else if (f < 1792) {
            int fb = f - 768; int mat = fb >= 512; int f2 = fb - mat * 512;
            int n = f2 >> 3, v = f2 & 7;
            pf[i] = *(const uint4*)((mat ? hin16 : x16) + (size_t)n * 1024 + v * 8);
        }
    }

    for (int kc = 0; kc < 1024; kc += 64) {
#pragma unroll
        for (int i = 0; i < 7; i++) {
            int f = tid + i * 256;
            if (f < 768) {
                int mat = f >= 384; int ff = f - mat * 384;
                int row = ff >> 3, v = ff & 7;
                *(uint4*)&As[mat * 3456 + row * 72 + v * 8] = pf[i];
            } else if (f < 1792) {
                int fb = f - 768; int mat = fb >= 512; int f2 = fb - mat * 512;
                int n = f2 >> 3, v = f2 & 7;
                *(uint4*)&Bs[mat * 4608 + n * 72 + v * 8] = pf[i];
            }
        }
        __syncthreads();
        if (kc + 64 < 1024) {
            int kn = kc + 64;
#pragma unroll
            for (int i = 0; i < 7; i++) {
                int f = tid + i * 256;
                if (f < 768) {
                    int mat = f >= 384; int ff = f - mat * 384;
                    int row = ff >> 3, v = ff & 7;
                    int grow = ((row >> 4) << 10) + J0 + (row & 15);
                    pf[i] = *(const uint4*)((mat ? Wh : Wi) + (size_t)grow * 1024 + kn + v * 8);
                } else if (f < 1792) {
                    int fb = f - 768; int mat = fb >= 512; int f2 = fb - mat * 512;
                    int n = f2 >> 3, v = f2 & 7;
                    pf[i] = *(const uint4*)((mat ? hin16 : x16) + (size_t)n * 1024 + kn + v * 8);
                }
            }
        }
        if (active) {
            const unsigned* Au = (const unsigned*)As;
            const unsigned* Bu = (const unsigned*)Bs;
#pragma unroll
            for (int kk = 0; kk < 4; kk++) {
                unsigned ai[4], ah[4];
                int abase = (g * 16 + r) * 36 + kk * 8 + cq;
                ai[0] = Au[abase]; ai[1] = Au[abase + 288];
                ai[2] = Au[abase + 4]; ai[3] = Au[abase + 292];
                ah[0] = Au[abase + 1728]; ah[1] = Au[abase + 2016];
                ah[2] = Au[abase + 1732]; ah[3] = Au[abase + 2020];
                unsigned bx[4][2], bh2[4][2];
#pragma unroll
                for (int j = 0; j < 4; j++) {
                    int bbase = (nh * 32 + j * 8 + r) * 36 + kk * 8 + cq;
                    bx[j][0] = Bu[bbase]; bx[j][1] = Bu[bbase + 4];
                    bh2[j][0] = Bu[bbase + 2304]; bh2[j][1] = Bu[bbase + 2308];
                }
#pragma unroll
                for (int j = 0; j < 4; j++) { mma16(accI[j], ai, bx[j]); mma16(accH[j], ah, bh2[j]); }
            }
        }
        __syncthreads();
    }

    if (active) {
#pragma unroll
        for (int j = 0; j < 4; j++) {
            int row0 = g * 16 + r;
            int col = nh * 32 + j * 8 + cq * 2;
            gi_s[row0 * 65 + col] = accI[j][0];       gi_s[row0 * 65 + col + 1] = accI[j][1];
            gi_s[(row0 + 8) * 65 + col] = accI[j][2]; gi_s[(row0 + 8) * 65 + col + 1] = accI[j][3];
            gh_s[row0 * 65 + col] = accH[j][0];       gh_s[row0 * 65 + col + 1] = accH[j][1];
            gh_s[(row0 + 8) * 65 + col] = accH[j][2]; gh_s[(row0 + 8) * 65 + col + 1] = accH[j][3];
        }
    }
    __syncthreads();
    for (int idx = tid; idx < 1024; idx += 256) {
        int jj = idx & 15, bb = idx >> 4;
        int j = J0 + jj;
        float ir = gi_s[jj * 65 + bb] + bi[j];
        float iz = gi_s[(16 + jj) * 65 + bb] + bi[1024 + j];
        float in_ = gi_s[(32 + jj) * 65 + bb] + bi[2048 + j];
        if (gix) {
            ir  += gix[(size_t)j * 960 + bb];
            iz  += gix[(size_t)(1024 + j) * 960 + bb];
            in_ += gix[(size_t)(2048 + j) * 960 + bb];
        }
        float hr = gh_s[jj * 65 + bb] + bh[j];
        float hz = gh_s[(16 + jj) * 65 + bb] + bh[1024 + j];
        float hn = gh_s[(32 + jj) * 65 + bb] + bh[2048 + j];
        float rr = 1.0f / (1.0f + expf(-(ir + hr)));
        float zz = 1.0f / (1.0f + expf(-(iz + hz)));
        float nn = tanhf(in_ + rr * hn);
        float hold = hin32[(size_t)j * 64 + bb];
        float val = (1.0f - zz) * nn + zz * hold;
        hout32[(size_t)j * 64 + bb] = val;
        hout16[(size_t)bb * 1024 + j] = __float2half_rn(val);
    }
    __syncthreads();
}

// ---------------- THE persistent decode loop ----------------
__global__ void __launch_bounds__(256, 1)
decode_loop(const __half* __restrict__ Wq16,
            const float* __restrict__ bq, const float* __restrict__ vvec,
            const float* __restrict__ bv,
            const __half* __restrict__ keys16, const __half* __restrict__ feat16,
            const __half* __restrict__ fc016, const float* __restrict__ fc0b,
            const __half* __restrict__ Wi0c, const __half* __restrict__ Wh016,
            const __half* __restrict__ WiL16, const __half* __restrict__ WhL16,
            const float* __restrict__ bi0, const float* __restrict__ bh0,
            const float* __restrict__ biL, const float* __restrict__ bhL,
            const float* __restrict__ giX,
            float* __restrict__ qp, float* __restrict__ qs,
            float* __restrict__ ebuf,
            __half* __restrict__ ctx16, float* __restrict__ fc0p,
            __half* __restrict__ ctxH16,
            float* __restrict__ h32A, float* __restrict__ h32B,
            __half* __restrict__ h16A, __half* __restrict__ h16B,
            __half* __restrict__ hAll16, const __half* __restrict__ zero16)
{
    __shared__ __align__(16) char pool[32768];
    int tid = threadIdx.x;
    int lane = tid & 31, w = tid >> 5;
    float bv0 = bv[0];

    for (int t = 0; t < CT; t++) {
        float*  cur32 = (t & 1) ? h32B : h32A;
        float*  nxt32 = (t & 1) ? h32A : h32B;
        __half* cur16 = (t & 1) ? h16B : h16A;
        __half* nxt16 = (t & 1) ? h16A : h16B;
        const __half* htop16 = (t == 0) ? zero16 : hAll16 + (size_t)(t - 1) * CB * CH;

        // Ph A: qp partials (64 units: 8 m-tiles x 8 k-chunks)
        for (int u = blockIdx.x; u < 64; u += NB) {
            int mt = u & 7, z = u >> 3;
            dev_gemm_h<true>(Wq16, htop16, qp + (size_t)z * CB * CH,
                             CH, CH, CH, CH, mt * 128, z * 128, 128, pool);
        }
        gbar();

        // Ph B: qsum
        for (int idx = blockIdx.x * 256 + tid; idx < CB * CH; idx += NB * 256) {
            int h = idx & 1023;
            float s = bq[h];
#pragma unroll
            for (int z = 0; z < 8; z++) s += qp[z * (CB * CH) + idx];
            qs[idx] = s;
        }
        gbar();

        // Ph C: energies (448 units: 64 b x 7 s-groups of 28)
        {
            float* qs_s = (float*)pool;
            for (int u = blockIdx.x; u < 448; u += NB) {
                int b = u / 7, sg = u % 7;
                __syncthreads();
                for (int i = tid; i < CH; i += 256) qs_s[i] = qs[b * CH + i];
                __syncthreads();
                for (int so = w; so < 28; so += 8) {
                    int s = sg * 28 + so;
                    const __half2* k2 = (const __half2*)(keys16 + ((size_t)b * CS + s) * CH);
                    const float2* v2 = (const float2*)vvec;
                    float partial = 0.0f;
#pragma unroll 4
                    for (int ii = lane; ii < 512; ii += 32) {
                        __half2 kh = k2[ii];
                        float2 vv = v2[ii];
                        partial += vv.x * fast_tanh(qs_s[2 * ii] + __low2float(kh));
                        partial += vv.y * fast_tanh(qs_s[2 * ii + 1] + __high2float(kh));
                    }
#pragma unroll
                    for (int o = 16; o > 0; o >>= 1)
                        partial += __shfl_xor_sync(0xffffffffu, partial, o);
                    if (lane == 0) ebuf[b * CS + s] = partial + bv0;
                }
            }
        }
        gbar();

        // Ph D: softmax + ctx (256 units: 32 kd-chunks x 8 b-groups; warp=one b)
        {
            float* ws = (float*)pool;   // [8][200]
            for (int u = blockIdx.x; u < 256; u += NB) {
                int c = u & 31, bg = u >> 5;
                int b = bg * 8 + w;
                float ev[7];
                float mx = -1e30f;
#pragma unroll
                for (int i = 0; i < 7; i++) {
                    int s = lane + i * 32;
                    ev[i] = (s < CS) ? ebuf[b * CS + s] : -1e30f;
                    mx = fmaxf(mx, ev[i]);
                }
#pragma unroll
                for (int o = 16; o > 0; o >>= 1) mx = fmaxf(mx, __shfl_xor_sync(0xffffffffu, mx, o));
                float sum = 0.0f;
#pragma unroll
                for (int i = 0; i < 7; i++) {
                    ev[i] = (lane + i * 32 < CS) ? __expf(ev[i] - mx) : 0.0f;
                    sum += ev[i];
                }
#pragma unroll
                for (int o = 16; o > 0; o >>= 1) sum += __shfl_xor_sync(0xffffffffu, sum, o);
                float inv = __fdividef(1.0f, sum);
#pragma unroll
                for (int i = 0; i < 7; i++) {
                    int s = lane + i * 32;
                    if (s < CS) ws[w * 200 + s] = ev[i] * inv;
                }
                __syncwarp();
                int kd = c * 32 + lane;
                const __half2* f2 = (const __half2*)(feat16 + (size_t)b * CS * CK);
                float ax = 0.0f, ay = 0.0f;
#pragma unroll 4
                for (int s = 0; s < CS; s++) {
                    __half2 hv = f2[(size_t)s * 1024 + kd];
                    float wv = ws[w * 200 + s];
                    ax = fmaf(wv, __low2float(hv), ax);
                    ay = fmaf(wv, __high2float(hv), ay);
                }
                ((__half2*)(ctx16 + (size_t)b * CK))[kd] = __floats2half2_rn(ax, ay);
                __syncwarp();
            }
        }
        gbar();

        // Ph E: fc0 partials (64 units: 8 m-tiles x 8 k-chunks of 256)
        for (int u = blockIdx.x; u < 64; u += NB) {
            int mt = u & 7, z = u >> 3;
            dev_gemm_h<false>(fc016, ctx16, fc0p + (size_t)z * CB * CH,
                              CH, CK, CK, 64, mt * 128, z * 256, 256, pool);
        }
        gbar();

        // Ph F: reduce fc0 -> ctxH16
        for (int idx = blockIdx.x * 256 + tid; idx < CB * CH; idx += NB * 256) {
            int j = idx >> 6, b = idx & 63;
            float s = fc0b[j];
#pragma unroll
            for (int z = 0; z < 8; z++) s += fc0p[z * (CB * CH) + idx];
            ctxH16[(size_t)b * CH + j] = __float2half_rn(s);
        }
        gbar();

        // Ph G-J: GRU layers
        for (int u = blockIdx.x; u < 64; u += NB)
            dev_gru(u * 16, Wi0c, Wh016, ctxH16, cur16, cur32, nxt32, nxt16,
                    giX + t * 64, bi0, bh0, pool);
        gbar();
        for (int l = 1; l < 3; l++) {
            for (int u = blockIdx.x; u < 64; u += NB)
                dev_gru(u * 16,
                        WiL16 + (size_t)(l - 1) * 3 * CH * CH,
                        WhL16 + (size_t)(l - 1) * 3 * CH * CH,
                        nxt16 + (size_t)(l - 1) * CB * CH,
                        cur16 + (size_t)l * CB * CH,
                        cur32 + (size_t)l * CB * CH,
                        nxt32 + (size_t)l * CB * CH,
                        nxt16 + (size_t)l * CB * CH,
                        nullptr,
                        biL + (size_t)(l - 1) * 3 * CH,
                        bhL + (size_t)(l - 1) * 3 * CH, pool);
            gbar();
        }
        for (int u = blockIdx.x; u < 64; u += NB)
            dev_gru(u * 16,
                    WiL16 + (size_t)2 * 3 * CH * CH,
                    WhL16 + (size_t)2 * 3 * CH * CH,
                    nxt16 + (size_t)2 * CB * CH,
                    htop16,
                    cur32 + (size_t)3 * CB * CH,
                    nxt32 + (size_t)3 * CB * CH,
                    hAll16 + (size_t)t * CB * CH,
                    nullptr,
                    biL + (size_t)2 * 3 * CH,
                    bhL + (size_t)2 * 3 * CH, pool);
        gbar();
    }
}

// ---------------- final batched fc2 ----------------
__global__ void __launch_bounds__(256)
gemm_fc2_final(const __half* __restrict__ A, const __half* __restrict__ B,
               const float* __restrict__ bias, float* __restrict__ out, int M)
{
    __shared__ __half As[128 * 40];
    __shared__ __half Bs[64 * 40];
    int tid = threadIdx.x;
    int lane = tid & 31, w = tid >> 5;
    int wm = (w & 3) * 32, wn = (w >> 2) * 32;
    int bm = blockIdx.y * 128;
    int bn = blockIdx.x * 64;
    B += (size_t)bn * CH;

    float acc[2][4][4] = {};
    uint4 apf[2], bpf;
    {
#pragma unroll
        for (int i = 0; i < 2; i++) {
            int f = tid + i * 256, row = f >> 2, v = f & 3;
            int gm = bm + row; if (gm >= M) gm = M - 1;
            apf[i] = *(const uint4*)(A + (size_t)gm * CH + v * 8);
        }
        { int n = tid >> 2, v = tid & 3;
          bpf = *(const uint4*)(B + (size_t)n * CH + v * 8); }
    }
    for (int kc = 0; kc < CH; kc += 32) {
#pragma unroll
        for (int i = 0; i < 2; i++) {
            int f = tid + i * 256, row = f >> 2, v = f & 3;
            *(uint4*)&As[row * 40 + v * 8] = apf[i];
        }
        { int n = tid >> 2, v = tid & 3;
          *(uint4*)&Bs[n * 40 + v * 8] = bpf; }
        __syncthreads();
        if (kc + 32 < CH) {
            int kn = kc + 32;
#pragma unroll
            for (int i = 0; i < 2; i++) {
                int f = tid + i * 256, row = f >> 2, v = f & 3;
                int gm = bm + row; if (gm >= M) gm = M - 1;
                apf[i] = *(const uint4*)(A + (size_t)gm * CH + kn + v * 8);
            }
            { int n = tid >> 2, v = tid & 3;
              bpf = *(const uint4*)(B + (size_t)n * CH + kn + v * 8); }
        }
        const unsigned* Au = (const unsigned*)As;
        const unsigned* Bu = (const unsigned*)Bs;
        int r = lane >> 2, cq = lane & 3;
#pragma unroll
        for (int kk = 0; kk < 2; kk++) {
            unsigned a[2][4], bf[4][2];
#pragma unroll
            for (int t = 0; t < 2; t++) {
                int base = (wm + t * 16 + r) * 20 + kk * 8 + cq;
                a[t][0] = Au[base]; a[t][1] = Au[base + 160];
                a[t][2] = Au[base + 4]; a[t][3] = Au[base + 164];
            }
#pragma unroll
            for (int j = 0; j < 4; j++) {
                int base = (wn + j * 8 + r) * 20 + kk * 8 + cq;
                bf[j][0] = Bu[base]; bf[j][1] = Bu[base + 4];
            }
#pragma unroll
            for (int t = 0; t < 2; t++)
#pragma unroll
                for (int j = 0; j < 4; j++)
                    mma16(acc[t][j], a[t], bf[j]);
        }
        __syncthreads();
    }
    int r = lane >> 2, cq = lane & 3;
#pragma unroll
    for (int t = 0; t < 2; t++) {
#pragma unroll
        for (int j = 0; j < 4; j++) {
            int row0 = bm + wm + t * 16 + r;
            int n = bn + wn + j * 8 + cq * 2;
            int tt = n >> 6, bb = n & 63;
            float* ac = acc[t][j];
            if (row0 < M) {
                float bz = bias[row0];
                out[((size_t)bb * CT + tt) * CV + row0] = ac[0] + bz;
                out[((size_t)(bb + 1) * CT + tt) * CV + row0] = ac[1] + bz;
            }
            if (row0 + 8 < M) {
                float bz = bias[row0 + 8];
                out[((size_t)bb * CT + tt) * CV + row0 + 8] = ac[2] + bz;
                out[((size_t)(bb + 1) * CT + tt) * CV + row0 + 8] = ac[3] + bz;
            }
        }
    }
}

// ---------------- misc kernels ----------------
__global__ void zerok(float* p, int n) {
    int i = blockIdx.x * 256 + threadIdx.x;
    if (i < n) p[i] = 0.0f;
}

__global__ void gather_emb(const float* __restrict__ emb,
                           const int* __restrict__ captions,
                           const int* __restrict__ sos,
                           float* __restrict__ xemb) {
    int m = blockIdx.x;
    int b = m & 63, t = m >> 6;
    int tok = (t == 0) ? sos[0] : captions[b * 16 + t];
    const float4* src = (const float4*)(emb + (size_t)tok * CE);
    float4* dst = (float4*)(xemb + (size_t)m * CE);
    dst[threadIdx.x] = src[threadIdx.x];
}

__global__ void transpose_h(const float* __restrict__ in, __half* __restrict__ out,
                            int R, int Cc) {
    __shared__ float t[32][33];
    int c = blockIdx.x * 32 + threadIdx.x;
    int r = blockIdx.y * 32 + threadIdx.y;
#pragma unroll
    for (int i = 0; i < 4; i++) {
        int rr = r + i * 8;
        if (rr < R && c < Cc) t[threadIdx.y + i * 8][threadIdx.x] = in[(size_t)rr * Cc + c];
    }
    __syncthreads();
    int c2 = blockIdx.y * 32 + threadIdx.x;
    int r2 = blockIdx.x * 32 + threadIdx.y;
#pragma unroll
    for (int i = 0; i < 4; i++) {
        int rr = r2 + i * 8;
        if (rr < Cc && c2 < R)
            out[(size_t)rr * R + c2] = __float2half_rn(t[threadIdx.x][threadIdx.y + i * 8]);
    }
}

__global__ void conv_h(const float* __restrict__ in, __half* __restrict__ out, int n2) {
    int i = blockIdx.x * 256 + threadIdx.x;
    if (i < n2) {
        float2 v = ((const float2*)in)[i];
        ((__half2*)out)[i] = __floats2half2_rn(v.x, v.y);
    }
}

__global__ void conv_wi0c(const float* __restrict__ in, __half* __restrict__ out) {
    int i = blockIdx.x * 256 + threadIdx.x;
    int r = i >> 9, c2 = (i & 511) * 2;
    float2 v = *(const float2*)(in + (size_t)r * 2048 + 1024 + c2);
    ((__half2*)out)[i] = __floats2half2_rn(v.x, v.y);
}

// ---------------- host launcher ----------------
extern "C" void kernel_launch(void* const* d_in, const int* in_sizes, int n_in,
                              void* d_out, int out_size) {
    const float* features = (const float*)d_in[0];
    const int*   captions = (const int*)d_in[1];
    const int*   sos      = (const int*)d_in[2];
    const float* emb      = (const float*)d_in[3];
    const float* fc1_W    = (const float*)d_in[4];
    const float* fc1_b    = (const float*)d_in[5];
    const float* attn_Wq  = (const float*)d_in[6];
    const float* attn_bq  = (const float*)d_in[7];
    const float* attn_Wk  = (const float*)d_in[8];
    const float* attn_bk  = (const float*)d_in[9];
    const float* attn_v   = (const float*)d_in[10];
    const float* attn_bv  = (const float*)d_in[11];
    const float* fc0_W    = (const float*)d_in[12];
    const float* fc0_b    = (const float*)d_in[13];
    const float* Wi0      = (const float*)d_in[14];
    const float* Wh0      = (const float*)d_in[15];
    const float* bi0      = (const float*)d_in[16];
    const float* bh0      = (const float*)d_in[17];
    const float* WiL      = (const float*)d_in[18];
    const float* WhL      = (const float*)d_in[19];
    const float* biL      = (const float*)d_in[20];
    const float* bhL      = (const float*)d_in[21];
    const float* fc2_W    = (const float*)d_in[22];
    const float* fc2_b    = (const float*)d_in[23];
    float* out = (float*)d_out;

    float* sc = nullptr;
    cudaGetSymbolAddress((void**)&sc, g_scratch);
    float*  xemb   = sc + OFF_XEMB;
    float*  xseqT  = sc + OFF_XSEQT;
    float*  giX    = sc + OFF_GIX;
    __half* keys16 = (__half*)(sc + OFF_KEYS16);
    __half* feat16 = (__half*)(sc + OFF_FEAT16);
    __half* Wq16   = (__half*)(sc + OFF_WQ16);
    __half* fc016  = (__half*)(sc + OFF_FC016);
    __half* fc216  = (__half*)(sc + OFF_FC216);
    __half* Wi0c   = (__half*)(sc + OFF_WI0C);
    __half* Wh016  = (__half*)(sc + OFF_WH016);
    __half* WiL16  = (__half*)(sc + OFF_WIL16);
    __half* WhL16  = (__half*)(sc + OFF_WHL16);
    float*  ebuf   = sc + OFF_E;
    float*  qp     = sc + OFF_QP;
    float*  qs     = sc + OFF_QS;
    __half* ctx16  = (__half*)(sc + OFF_CTX16);
    __half* ctxH16 = (__half*)(sc + OFF_CTXH16);
    float*  h32A   = sc + OFF_H32A;
    float*  h32B   = sc + OFF_H32B;
    __half* h16A   = (__half*)(sc + OFF_H16A);
    __half* h16B   = (__half*)(sc + OFF_H16B);
    float*  fc0p   = sc + OFF_FC0P;
    __half* hAll16 = (__half*)(sc + OFF_HALL);
    __half* zero16 = h16A + 3 * CB * CH;

    zerok<<<1024, 256>>>(h32A, 4 * CB * CH);
    zerok<<<512, 256>>>((float*)h16A, 2 * CB * CH);
    gather_emb<<<CB * CT, 128>>>(emb, captions, sos, xemb);

    transpose_h<<<dim3(32, 32), dim3(32, 8)>>>(attn_Wq, Wq16, CH, CH);
    transpose_h<<<dim3(32, 64), dim3(32, 8)>>>(fc0_W, fc016, CK, CH);
    transpose_h<<<dim3((CV + 31) / 32, 32), dim3(32, 8)>>>(fc2_W, fc216, CH, CV);
    conv_wi0c<<<(3072 * 512 + 255) / 256, 256>>>(Wi0, Wi0c);
    conv_h<<<(3072 * 512 + 255) / 256, 256>>>(Wh0, Wh016, 3072 * 512);
    conv_h<<<(3 * 3072 * 512 + 255) / 256, 256>>>(WiL, WiL16, 3 * 3072 * 512);
    conv_h<<<(3 * 3072 * 512 + 255) / 256, 256>>>(WhL, WhL16, 3 * 3072 * 512);
    conv_h<<<(CB * CS * CK / 2 + 255) / 256, 256>>>(features, feat16, CB * CS * CK / 2);

    gemm_tf32<true, false><<<dim3(16, 8, 1), 256>>>(xemb, fc1_W, fc1_b, xseqT,
                                                    960, CE, CE, CH, 960, 0);
    gemm_tf32<false, false><<<dim3(15, 24, 1), 256>>>(Wi0, xseqT, nullptr, giX,
                                                      3 * CH, CH, 2 * CH, 960, 960, 0);
    gemm_tf32<false, true><<<dim3(16, 98, 1), 256>>>(features, attn_Wk, attn_bk,
                                                     (float*)keys16,
                                                     CB * CS, CK, CK, CH, CH, 0);

    decode_loop<<<NB, 256>>>(Wq16, attn_bq, attn_v, attn_bv, keys16, feat16,
                             fc016, fc0_b, Wi0c, Wh016, WiL16, WhL16,
                             bi0, bh0, biL, bhL, giX,
                             qp, qs, ebuf, ctx16, fc0p, ctxH16,
                             h32A, h32B, h16A, h16B, hAll16, zero16);

    gemm_fc2_final<<<dim3(15, 79), 256>>>(fc216, hAll16, fc2_b, out, CV);
}

// round 12
// speedup vs baseline: 1.2878x; 1.2878x over previous
#include <cuda_runtime.h>
#include <cuda_fp16.h>
#include <math.h>

#define CV 10000
#define CE 512
#define CH 1024
#define CK 2048
#define CB 64
#define CS 196
#define CT 15

// ---------------- scratch layout (float units, 16B-aligned) ----------------
#define OFF_XEMB    0u
#define OFF_XSEQ16  491520u     // [960][1024] halves
#define OFF_GIX     1474560u    // [3072][960] f32
#define OFF_KEYS16  4423680u
#define OFF_FEAT16  10846208u
#define OFF_WQ16    23691264u
#define OFF_FC016   24215552u
#define OFF_FC216   25264128u
#define OFF_WI0C    30384128u
#define OFF_WH016   31956992u
#define OFF_WIL16   33529856u
#define OFF_WHL16   38248448u
#define OFF_E       42967040u
#define OFF_QP      42992128u
#define OFF_CTX16   43581952u
#define OFF_CTXH16  43647488u
#define OFF_H32A    43680256u
#define OFF_H32B    43942400u
#define OFF_H16A    44204544u
#define OFF_H16B    44335616u
#define OFF_FC0P    44466688u
#define OFF_HALL    44990976u
#define OFF_WKT16   45482496u   // [1024][2048] halves
#define OFF_WI0X    46531072u   // [3072][1024] halves
#define SCRATCH_TOTAL 48103936u

__device__ __align__(16) float g_scratch[SCRATCH_TOTAL];

__device__ __forceinline__ float fast_tanh(float x) {
    float e = __expf(2.0f * x);
    return 1.0f - __fdividef(2.0f, 1.0f + e);
}

__device__ __forceinline__ float tf32r(float x) {
    unsigned u;
    asm("cvt.rna.tf32.f32 %0, %1;" : "=r"(u) : "f"(x));
    return __uint_as_float(u);
}

__device__ __forceinline__ void mma8(float* c, const unsigned* a, const unsigned* b) {
    asm volatile(
        "mma.sync.aligned.m16n8k8.row.col.f32.tf32.tf32.f32 "
        "{%0,%1,%2,%3}, {%4,%5,%6,%7}, {%8,%9}, {%0,%1,%2,%3};\n"
        : "+f"(c[0]), "+f"(c[1]), "+f"(c[2]), "+f"(c[3])
        : "r"(a[0]), "r"(a[1]), "r"(a[2]), "r"(a[3]), "r"(b[0]), "r"(b[1]));
}

__device__ __forceinline__ void mma16(float* c, const unsigned* a, const unsigned* b) {
    asm volatile(
        "mma.sync.aligned.m16n8k16.row.col.f32.f16.f16.f32 "
        "{%0,%1,%2,%3}, {%4,%5,%6,%7}, {%8,%9}, {%0,%1,%2,%3};\n"
        : "+f"(c[0]), "+f"(c[1]), "+f"(c[2]), "+f"(c[3])
        : "r"(a[0]), "r"(a[1]), "r"(a[2]), "r"(a[3]), "r"(b[0]), "r"(b[1]));
}

// ---------------- tf32 GEMM (prologue: fc1 only). HOUT: fp16 out -----------
template<bool STORE_T, bool HOUT>
__global__ void __launch_bounds__(256)
gemm_tf32(const float* __restrict__ A, const float* __restrict__ B,
          const float* __restrict__ bias, float* __restrict__ C,
          int M, int K, int lda, int ldb, int ldc, size_t zstride)
{
    __shared__ float As[128 * 44];
    __shared__ float Bs[32 * 72];
    int tid = threadIdx.x;
    int lane = tid & 31, w = tid >> 5;
    int wm = (w & 3) * 32, wn = (w >> 2) * 32;
    int bn = blockIdx.x * 64, bm = blockIdx.y * 128;
    int kper = K / gridDim.z;
    int k0 = blockIdx.z * kper, kend = k0 + kper;
    C += (size_t)blockIdx.z * zstride;

    float acc[2][4][4] = {};
    float4 apf[4], bpf[2];
    {
        int kc = k0;
#pragma unroll
        for (int i = 0; i < 4; i++) {
            int f = tid + i * 256, m = f >> 3, k4 = f & 7;
            int gm = bm + m; if (gm >= M) gm = M - 1;
            apf[i] = *(const float4*)(A + (size_t)gm * lda + kc + k4 * 4);
        }
#pragma unroll
        for (int i = 0; i < 2; i++) {
            int f = tid + i * 256, kr = f >> 4, n4 = f & 15;
            bpf[i] = *(const float4*)(B + (size_t)(kc + kr) * ldb + bn + n4 * 4);
        }
    }
    for (int kc = k0; kc < kend; kc += 32) {
#pragma unroll
        for (int i = 0; i < 4; i++) {
            int f = tid + i * 256, m = f >> 3, k4 = f & 7;
            float4 v = apf[i];
            *(float4*)&As[m * 44 + k4 * 4] =
                make_float4(tf32r(v.x), tf32r(v.y), tf32r(v.z), tf32r(v.w));
        }
#pragma unroll
        for (int i = 0; i < 2; i++) {
            int f = tid + i * 256, kr = f >> 4, n4 = f & 15;
            float4 v = bpf[i];
            *(float4*)&Bs[kr * 72 + n4 * 4] =
                make_float4(tf32r(v.x), tf32r(v.y), tf32r(v.z), tf32r(v.w));
        }
        __syncthreads();
        if (kc + 32 < kend) {
            int kn = kc + 32;
#pragma unroll
            for (int i = 0; i < 4; i++) {
                int f = tid + i * 256, m = f >> 3, k4 = f & 7;
                int gm = bm + m; if (gm >= M) gm = M - 1;
                apf[i] = *(const float4*)(A + (size_t)gm * lda + kn + k4 * 4);
            }
#pragma unroll
            for (int i = 0; i < 2; i++) {
                int f = tid + i * 256, kr = f >> 4, n4 = f & 15;
                bpf[i] = *(const float4*)(B + (size_t)(kn + kr) * ldb + bn + n4 * 4);
            }
        }
        const unsigned* Asu = (const unsigned*)As;
        const unsigned* Bsu = (const unsigned*)Bs;
        int r = lane >> 2, cq = lane & 3;
#pragma unroll
        for (int kk = 0; kk < 4; kk++) {
            unsigned a[2][4], bf[4][2];
#pragma unroll
            for (int t = 0; t < 2; t++) {
                int base = (wm + t * 16 + r) * 44 + kk * 8 + cq;
                a[t][0] = Asu[base]; a[t][1] = Asu[base + 8 * 44];
                a[t][2] = Asu[base + 4]; a[t][3] = Asu[base + 8 * 44 + 4];
            }
#pragma unroll
            for (int j = 0; j < 4; j++) {
                int base = (kk * 8 + cq) * 72 + wn + j * 8 + r;
                bf[j][0] = Bsu[base]; bf[j][1] = Bsu[base + 4 * 72];
            }
#pragma unroll
            for (int t = 0; t < 2; t++)
#pragma unroll
                for (int j = 0; j < 4; j++)
                    mma8(acc[t][j], a[t], bf[j]);
        }
        __syncthreads();
    }
    int r = lane >> 2, cq = lane & 3;
#pragma unroll
    for (int t = 0; t < 2; t++) {
#pragma unroll
        for (int j = 0; j < 4; j++) {
            int row0 = bm + wm + t * 16 + r;
            int col = bn + wn + j * 8 + cq * 2;
            float* ac = acc[t][j];
            float b0 = bias ? bias[col] : 0.0f;
            float b1 = bias ? bias[col + 1] : 0.0f;
            if (STORE_T) {
                if (row0 < M) {
                    C[(size_t)col * ldc + row0] = ac[0] + b0;
                    C[(size_t)(col + 1) * ldc + row0] = ac[1] + b1;
                }
                if (row0 + 8 < M) {
                    C[(size_t)col * ldc + row0 + 8] = ac[2] + b0;
                    C[(size_t)(col + 1) * ldc + row0 + 8] = ac[3] + b1;
                }
            } else if (HOUT) {
                __half* Ch = (__half*)C;
                if (row0 < M)
                    *(__half2*)(Ch + (size_t)row0 * ldc + col) = __floats2half2_rn(ac[0] + b0, ac[1] + b1);
                if (row0 + 8 < M)
                    *(__half2*)(Ch + (size_t)(row0 + 8) * ldc + col) = __floats2half2_rn(ac[2] + b0, ac[3] + b1);
            } else {
                if (row0 < M)
                    *(float2*)(C + (size_t)row0 * ldc + col) = make_float2(ac[0] + b0, ac[1] + b1);
                if (row0 + 8 < M)
                    *(float2*)(C + (size_t)(row0 + 8) * ldc + col) = make_float2(ac[2] + b0, ac[3] + b1);
            }
        }
    }
}

// ---------------- fp16 GEMM: A fp16 [M][K], B fp16 [N][K] row-major ---------
// C = A @ B^T. Tile 128m x 64n x 32k. blockIdx.x = n-tile; blockIdx.z = split-K.
template<bool STORE_T, bool HOUT>
__global__ void __launch_bounds__(256)
gemm_h(const __half* __restrict__ A, const __half* __restrict__ B,
       const float* __restrict__ bias, float* __restrict__ C,
       int M, int K, int lda, int ldb, int ldc, size_t zstride)
{
    __shared__ __half As[128 * 40];
    __shared__ __half Bs[64 * 40];
    int tid = threadIdx.x;
    int lane = tid & 31, w = tid >> 5;
    int wm = (w & 3) * 32, wn = (w >> 2) * 32;
    int bm = blockIdx.y * 128;
    int bn = blockIdx.x * 64;
    B += (size_t)bn * ldb;
    int kper = K / gridDim.z;
    int k0 = blockIdx.z * kper, kend = k0 + kper;
    C += (size_t)blockIdx.z * zstride;

    float acc[2][4][4] = {};
    uint4 apf[2], bpf;
    {
#pragma unroll
        for (int i = 0; i < 2; i++) {
            int f = tid + i * 256, row = f >> 2, v = f & 3;
            int gm = bm + row; if (gm >= M) gm = M - 1;
            apf[i] = *(const uint4*)(A + (size_t)gm * lda + k0 + v * 8);
        }
        { int n = tid >> 2, v = tid & 3;
          bpf = *(const uint4*)(B + (size_t)n * ldb + k0 + v * 8); }
    }
    for (int kc = k0; kc < kend; kc += 32) {
#pragma unroll
        for (int i = 0; i < 2; i++) {
            int f = tid + i * 256, row = f >> 2, v = f & 3;
            *(uint4*)&As[row * 40 + v * 8] = apf[i];
        }
        { int n = tid >> 2, v = tid & 3;
          *(uint4*)&Bs[n * 40 + v * 8] = bpf; }
        __syncthreads();
        if (kc + 32 < kend) {
            int kn = kc + 32;
#pragma unroll
            for (int i = 0; i < 2; i++) {
                int f = tid + i * 256, row = f >> 2, v = f & 3;
                int gm = bm + row; if (gm >= M) gm = M - 1;
                apf[i] = *(const uint4*)(A + (size_t)gm * lda + kn + v * 8);
            }
            { int n = tid >> 2, v = tid & 3;
              bpf = *(const uint4*)(B + (size_t)n * ldb + kn + v * 8); }
        }
        const unsigned* Au = (const unsigned*)As;
        const unsigned* Bu = (const unsigned*)Bs;
        int r = lane >> 2, cq = lane & 3;
#pragma unroll
        for (int kk = 0; kk < 2; kk++) {
            unsigned a[2][4], bf[4][2];
#pragma unroll
            for (int t = 0; t < 2; t++) {
                int base = (wm + t * 16 + r) * 20 + kk * 8 + cq;
                a[t][0] = Au[base]; a[t][1] = Au[base + 160];
                a[t][2] = Au[base + 4]; a[t][3] = Au[base + 164];
            }
#pragma unroll
            for (int j = 0; j < 4; j++) {
                int base = (wn + j * 8 + r) * 20 + kk * 8 + cq;
                bf[j][0] = Bu[base]; bf[j][1] = Bu[base + 4];
            }
#pragma unroll
            for (int t = 0; t < 2; t++)
#pragma unroll
                for (int j = 0; j < 4; j++)
                    mma16(acc[t][j], a[t], bf[j]);
        }
        __syncthreads();
    }
    int r = lane >> 2, cq = lane & 3;
#pragma unroll
    for (int t = 0; t < 2; t++) {
#pragma unroll
        for (int j = 0; j < 4; j++) {
            int row0 = bm + wm + t * 16 + r;
            int colg = bn + wn + j * 8 + cq * 2;
            float* ac = acc[t][j];
            float b0 = bias ? bias[colg] : 0.0f;
            float b1 = bias ? bias[colg + 1] : 0.0f;
            if (STORE_T) {
                if (row0 < M) {
                    C[(size_t)colg * ldc + row0] = ac[0] + b0;
                    C[(size_t)(colg + 1) * ldc + row0] = ac[1] + b1;
                }
                if (row0 + 8 < M) {
                    C[(size_t)colg * ldc + row0 + 8] = ac[2] + b0;
                    C[(size_t)(colg + 1) * ldc + row0 + 8] = ac[3] + b1;
                }
            } else if (HOUT) {
                __half* Ch = (__half*)C;
                if (row0 < M)
                    *(__half2*)(Ch + (size_t)row0 * ldc + colg) = __floats2half2_rn(ac[0] + b0, ac[1] + b1);
                if (row0 + 8 < M)
                    *(__half2*)(Ch + (size_t)(row0 + 8) * ldc + colg) = __floats2half2_rn(ac[2] + b0, ac[3] + b1);
            } else {
                if (row0 < M)
                    *(float2*)(C + (size_t)row0 * ldc + colg) = make_float2(ac[0] + b0, ac[1] + b1);
                if (row0 + 8 < M)
                    *(float2*)(C + (size_t)(row0 + 8) * ldc + colg) = make_float2(ac[2] + b0, ac[3] + b1);
            }
        }
    }
}

// ---------------- final batched fc2 ----------------
__global__ void __launch_bounds__(256)
gemm_fc2_final(const __half* __restrict__ A, const __half* __restrict__ B,
               const float* __restrict__ bias, float* __restrict__ out, int M)
{
    __shared__ __half As[128 * 40];
    __shared__ __half Bs[64 * 40];
    int tid = threadIdx.x;
    int lane = tid & 31, w = tid >> 5;
    int wm = (w & 3) * 32, wn = (w >> 2) * 32;
    int bm = blockIdx.y * 128;
    int bn = blockIdx.x * 64;
    B += (size_t)bn * CH;

    float acc[2][4][4] = {};
    uint4 apf[2], bpf;
    {
#pragma unroll
        for (int i = 0; i < 2; i++) {
            int f = tid + i * 256, row = f >> 2, v = f & 3;
            int gm = bm + row; if (gm >= M) gm = M - 1;
            apf[i] = *(const uint4*)(A + (size_t)gm * CH + v * 8);
        }
        { int n = tid >> 2, v = tid & 3;
          bpf = *(const uint4*)(B + (size_t)n * CH + v * 8); }
    }
    for (int kc = 0; kc < CH; kc += 32) {
#pragma unroll
        for (int i = 0; i < 2; i++) {
            int f = tid + i * 256, row = f >> 2, v = f & 3;
            *(uint4*)&As[row * 40 + v * 8] = apf[i];
        }
        { int n = tid >> 2, v = tid & 3;
          *(uint4*)&Bs[n * 40 + v * 8] = bpf; }
        __syncthreads();
        if (kc + 32 < CH) {
            int kn = kc + 32;
#pragma unroll
            for (int i = 0; i < 2; i++) {
                int f = tid + i * 256, row = f >> 2, v = f & 3;
                int gm = bm + row; if (gm >= M) gm = M - 1;
                apf[i] = *(const uint4*)(A + (size_t)gm * CH + kn + v * 8);
            }
            { int n = tid >> 2, v = tid & 3;
              bpf = *(const uint4*)(B + (size_t)n * CH + kn + v * 8); }
        }
        const unsigned* Au = (const unsigned*)As;
        const unsigned* Bu = (const unsigned*)Bs;
        int r = lane >> 2, cq = lane & 3;
#pragma unroll
        for (int kk = 0; kk < 2; kk++) {
            unsigned a[2][4], bf[4][2];
#pragma unroll
            for (int t = 0; t < 2; t++) {
                int base = (wm + t * 16 + r) * 20 + kk * 8 + cq;
                a[t][0] = Au[base]; a[t][1] = Au[base + 160];
                a[t][2] = Au[base + 4]; a[t][3] = Au[base + 164];
            }
#pragma unroll
            for (int j = 0; j < 4; j++) {
                int base = (wn + j * 8 + r) * 20 + kk * 8 + cq;
                bf[j][0] = Bu[base]; bf[j][1] = Bu[base + 4];
            }
#pragma unroll
            for (int t = 0; t < 2; t++)
#pragma unroll
                for (int j = 0; j < 4; j++)
                    mma16(acc[t][j], a[t], bf[j]);
        }
        __syncthreads();
    }
    int r = lane >> 2, cq = lane & 3;
#pragma unroll
    for (int t = 0; t < 2; t++) {
#pragma unroll
        for (int j = 0; j < 4; j++) {
            int row0 = bm + wm + t * 16 + r;
            int n = bn + wn + j * 8 + cq * 2;
            int tt = n >> 6, bb = n & 63;
            float* ac = acc[t][j];
            if (row0 < M) {
                float bz = bias[row0];
                out[((size_t)bb * CT + tt) * CV + row0] = ac[0] + bz;
                out[((size_t)(bb + 1) * CT + tt) * CV + row0] = ac[1] + bz;
            }
            if (row0 + 8 < M) {
                float bz = bias[row0 + 8];
                out[((size_t)bb * CT + tt) * CV + row0 + 8] = ac[2] + bz;
                out[((size_t)(bb + 1) * CT + tt) * CV + row0 + 8] = ac[3] + bz;
            }
        }
    }
}

// ---------------- fused GRU layer, fp16, BK=64, full 64-batch tile -----------
__global__ void __launch_bounds__(192)
gru_h(const __half* __restrict__ Wi, const __half* __restrict__ Wh,
      const __half* __restrict__ x16, const __half* __restrict__ hin16,
      const float* __restrict__ hin32, float* __restrict__ hout32,
      __half* __restrict__ hout16, const float* __restrict__ gix,
      const float* __restrict__ bi, const float* __restrict__ bh)
{
    __shared__ float pool[8064];
    __half* As = (__half*)pool;
    __half* Bs = (__half*)(pool + 3456);
    float* gi_s = pool;
    float* gh_s = pool + 3120;

    int tid = threadIdx.x;
    int lane = tid & 31, w = tid >> 5;
    int J0 = blockIdx.x * 16;
    int g = w >> 1, nh = w & 1;
    int r = lane >> 2, cq = lane & 3;

    float accI[4][4] = {}, accH[4][4] = {};
    uint4 pf[10];

#pragma unroll
    for (int i = 0; i < 10; i++) {
        int f = tid + i * 192;
        if (f < 768) {
            int mat = f >= 384; int ff = f - mat * 384;
            int row = ff >> 3, v = ff & 7;
            int grow = ((row >> 4) << 10) + J0 + (row & 15);
            pf[i] = *(const uint4*)((mat ? Wh : Wi) + (size_t)grow * 1024 + v * 8);
        } else if (f < 1792) {
            int fb = f - 768; int mat = fb >= 512; int f2 = fb - mat * 512;
            int n = f2 >> 3, v = f2 & 7;
            pf[i] = *(const uint4*)((mat ? hin16 : x16) + (size_t)n * 1024 + v * 8);
        }
    }

    for (int kc = 0; kc < 1024; kc += 64) {
#pragma unroll
        for (int i = 0; i < 10; i++) {
            int f = tid + i * 192;
            if (f < 768) {
                int mat = f >= 384; int ff = f - mat * 384;
                int row = ff >> 3, v = ff & 7;
                *(uint4*)&As[mat * 3456 + row * 72 + v * 8] = pf[i];
            } else if (f < 1792) {
                int fb = f - 768; int mat = fb >= 512; int f2 = fb - mat * 512;
                int n = f2 >> 3, v = f2 & 7;
                *(uint4*)&Bs[mat * 4608 + n * 72 + v * 8] = pf[i];
            }
        }
        __syncthreads();
        if (kc + 64 < 1024) {
            int kn = kc + 64;
#pragma unroll
            for (int i = 0; i < 10; i++) {
                int f = tid + i * 192;
                if (f < 768) {
                    int mat = f >= 384; int ff = f - mat * 384;
                    int row = ff >> 3, v = ff & 7;
                    int grow = ((row >> 4) << 10) + J0 + (row & 15);
                    pf[i] = *(const uint4*)((mat ? Wh : Wi) + (size_t)grow * 1024 + kn + v * 8);
                } else if (f < 1792) {
                    int fb = f - 768; int mat = fb >= 512; int f2 = fb - mat * 512;
                    int n = f2 >> 3, v = f2 & 7;
                    pf[i] = *(const uint4*)((mat ? hin16 : x16) + (size_t)n * 1024 + kn + v * 8);
                }
            }
        }
        const unsigned* Au = (const unsigned*)As;
        const unsigned* Bu = (const unsigned*)Bs;
#pragma unroll
        for (int kk = 0; kk < 4; kk++) {
            unsigned ai[4], ah[4];
            int abase = (g * 16 + r) * 36 + kk * 8 + cq;
            ai[0] = Au[abase]; ai[1] = Au[abase + 288];
            ai[2] = Au[abase + 4]; ai[3] = Au[abase + 292];
            ah[0] = Au[abase + 1728]; ah[1] = Au[abase + 2016];
            ah[2] = Au[abase + 1732]; ah[3] = Au[abase + 2020];
            unsigned bx[4][2], bh2[4][2];
#pragma unroll
            for (int j = 0; j < 4; j++) {
                int bbase = (nh * 32 + j * 8 + r) * 36 + kk * 8 + cq;
                bx[j][0] = Bu[bbase]; bx[j][1] = Bu[bbase + 4];
                bh2[j][0] = Bu[bbase + 2304]; bh2[j][1] = Bu[bbase + 2308];
            }
#pragma unroll
            for (int j = 0; j < 4; j++) { mma16(accI[j], ai, bx[j]); mma16(accH[j], ah, bh2[j]); }
        }
        __syncthreads();
    }

#pragma unroll
    for (int j = 0; j < 4; j++) {
        int row0 = g * 16 + r;
        int col = nh * 32 + j * 8 + cq * 2;
        gi_s[row0 * 65 + col] = accI[j][0];       gi_s[row0 * 65 + col + 1] = accI[j][1];
        gi_s[(row0 + 8) * 65 + col] = accI[j][2]; gi_s[(row0 + 8) * 65 + col + 1] = accI[j][3];
        gh_s[row0 * 65 + col] = accH[j][0];       gh_s[row0 * 65 + col + 1] = accH[j][1];
        gh_s[(row0 + 8) * 65 + col] = accH[j][2]; gh_s[(row0 + 8) * 65 + col + 1] = accH[j][3];
    }
    __syncthreads();
    for (int idx = tid; idx < 1024; idx += 192) {
        int jj = idx & 15, bb = idx >> 4;
        int j = J0 + jj;
        float ir = gi_s[jj * 65 + bb] + bi[j];
        float iz = gi_s[(16 + jj) * 65 + bb] + bi[1024 + j];
        float in_ = gi_s[(32 + jj) * 65 + bb] + bi[2048 + j];
        if (gix) {
            ir  += gix[(size_t)j * 960 + bb];
            iz  += gix[(size_t)(1024 + j) * 960 + bb];
            in_ += gix[(size_t)(2048 + j) * 960 + bb];
        }
        float hr = gh_s[jj * 65 + bb] + bh[j];
        float hz = gh_s[(16 + jj) * 65 + bb] + bh[1024 + j];
        float hn = gh_s[(32 + jj) * 65 + bb] + bh[2048 + j];
        float rr = 1.0f / (1.0f + expf(-(ir + hr)));
        float zz = 1.0f / (1.0f + expf(-(iz + hz)));
        float nn = tanhf(in_ + rr * hn);
        float hold = hin32[(size_t)j * 64 + bb];
        float val = (1.0f - zz) * nn + zz * hold;
        hout32[(size_t)j * 64 + bb] = val;
        hout16[(size_t)bb * 1024 + j] = __float2half_rn(val);
    }
}

// ---------------- misc kernels ----------------
__global__ void zerok(float* p, int n) {
    int i = blockIdx.x * 256 + threadIdx.x;
    if (i < n) p[i] = 0.0f;
}

__global__ void gather_emb(const float* __restrict__ emb,
                           const int* __restrict__ captions,
                           const int* __restrict__ sos,
                           float* __restrict__ xemb) {
    int m = blockIdx.x;
    int b = m & 63, t = m >> 6;
    int tok = (t == 0) ? sos[0] : captions[b * 16 + t];
    const float4* src = (const float4*)(emb + (size_t)tok * CE);
    float4* dst = (float4*)(xemb + (size_t)m * CE);
    dst[threadIdx.x] = src[threadIdx.x];
}

__global__ void transpose_h(const float* __restrict__ in, __half* __restrict__ out,
                            int R, int Cc) {
    __shared__ float t[32][33];
    int c = blockIdx.x * 32 + threadIdx.x;
    int r = blockIdx.y * 32 + threadIdx.y;
#pragma unroll
    for (int i = 0; i < 4; i++) {
        int rr = r + i * 8;
        if (rr < R && c < Cc) t[threadIdx.y + i * 8][threadIdx.x] = in[(size_t)rr * Cc + c];
    }
    __syncthreads();
    int c2 = blockIdx.y * 32 + threadIdx.x;
    int r2 = blockIdx.x * 32 + threadIdx.y;
#pragma unroll
    for (int i = 0; i < 4; i++) {
        int rr = r2 + i * 8;
        if (rr < Cc && c2 < R)
            out[(size_t)rr * R + c2] = __float2half_rn(t[threadIdx.x][threadIdx.y + i * 8]);
    }
}

__global__ void conv_h(const float* __restrict__ in, __half* __restrict__ out, int n2) {
    int i = blockIdx.x * 256 + threadIdx.x;
    if (i < n2) {
        float2 v = ((const float2*)in)[i];
        ((__half2*)out)[i] = __floats2half2_rn(v.x, v.y);
    }
}

// extract 1024-col half of a [3072][2048] matrix -> fp16 [3072][1024]
__global__ void conv_wi0half(const float* __restrict__ in, __half* __restrict__ out,
                             int coloff) {
    int i = blockIdx.x * 256 + threadIdx.x;   // 3072*512 half2
    int r = i >> 9, c2 = (i & 511) * 2;
    float2 v = *(const float2*)(in + (size_t)r * 2048 + coloff + c2);
    ((__half2*)out)[i] = __floats2half2_rn(v.x, v.y);
}

// fused qp-reduce + energies: grid (4 s-groups, 64 b), block 256
__global__ void e2_kernel(const float* __restrict__ qp, const float* __restrict__ bq,
                          const __half* __restrict__ keys16, const float* __restrict__ vvec,
                          const float* __restrict__ bv, float* __restrict__ ebuf) {
    __shared__ float qs_s[1024];
    int sg = blockIdx.x, b = blockIdx.y;
    int tid = threadIdx.x;
    int lane = tid & 31, w = tid >> 5;
    for (int i = tid; i < CH; i += 256) {
        float s = bq[i];
#pragma unroll
        for (int z = 0; z < 8; z++) s += qp[z * (CB * CH) + b * CH + i];
        qs_s[i] = s;
    }
    __syncthreads();
    float bv0 = bv[0];
    const float2* v2 = (const float2*)vvec;
    for (int s = sg * 49 + w; s < sg * 49 + 49; s += 8) {
        const __half2* k2 = (const __half2*)(keys16 + ((size_t)b * CS + s) * CH);
        float partial = 0.0f;
#pragma unroll 4
        for (int ii = lane; ii < 512; ii += 32) {
            __half2 kh = k2[ii];
            float2 vv = v2[ii];
            partial += vv.x * fast_tanh(qs_s[2 * ii] + __low2float(kh));
            partial += vv.y * fast_tanh(qs_s[2 * ii + 1] + __high2float(kh));
        }
#pragma unroll
        for (int o = 16; o > 0; o >>= 1)
            partial += __shfl_xor_sync(0xffffffffu, partial, o);
        if (lane == 0) ebuf[b * CS + s] = partial + bv0;
    }
}

// fused softmax + context: grid (32, 8), block 256 (8 warps; warp w owns b)
__global__ void ctxsm_h(const float* __restrict__ e, const __half* __restrict__ feat16,
                        __half* __restrict__ ctx16) {
    __shared__ float ws[8][200];
    int tid = threadIdx.x;
    int lane = tid & 31, w = tid >> 5;
    int b = blockIdx.y * 8 + w;

    float ev[7];
    float mx = -1e30f;
#pragma unroll
    for (int i = 0; i < 7; i++) {
        int s = lane + i * 32;
        ev[i] = (s < CS) ? e[b * CS + s] : -1e30f;
        mx = fmaxf(mx, ev[i]);
    }
#pragma unroll
    for (int o = 16; o > 0; o >>= 1) mx = fmaxf(mx, __shfl_xor_sync(0xffffffffu, mx, o));
    float sum = 0.0f;
#pragma unroll
    for (int i = 0; i < 7; i++) {
        ev[i] = (lane + i * 32 < CS) ? __expf(ev[i] - mx) : 0.0f;
        sum += ev[i];
    }
#pragma unroll
    for (int o = 16; o > 0; o >>= 1) sum += __shfl_xor_sync(0xffffffffu, sum, o);
    float inv = __fdividef(1.0f, sum);
#pragma unroll
    for (int i = 0; i < 7; i++) {
        int s = lane + i * 32;
        if (s < CS) ws[w][s] = ev[i] * inv;
    }
    __syncwarp();

    int kd = blockIdx.x * 32 + lane;
    const __half2* f2 = (const __half2*)(feat16 + (size_t)b * CS * CK);
    float ax = 0.0f, ay = 0.0f;
#pragma unroll 4
    for (int s = 0; s < CS; s++) {
        __half2 hv = f2[(size_t)s * 1024 + kd];
        float wv = ws[w][s];
        ax = fmaf(wv, __low2float(hv), ax);
        ay = fmaf(wv, __high2float(hv), ay);
    }
    ((__half2*)(ctx16 + (size_t)b * CK))[kd] = __floats2half2_rn(ax, ay);
}

__global__ void reduce64h(const float* __restrict__ part, const float* __restrict__ bias,
                          __half* __restrict__ out16, int z, size_t zstride) {
    int idx = blockIdx.x * 256 + threadIdx.x;
    int j = idx >> 6, b = idx & 63;
    float s = bias[j];
    for (int zz = 0; zz < z; zz++) s += part[zz * zstride + idx];
    out16[(size_t)b * 1024 + j] = __float2half_rn(s);
}

// ---------------- host launcher ----------------
extern "C" void kernel_launch(void* const* d_in, const int* in_sizes, int n_in,
                              void* d_out, int out_size) {
    const float* features = (const float*)d_in[0];
    const int*   captions = (const int*)d_in[1];
    const int*   sos      = (const int*)d_in[2];
    const float* emb      = (const float*)d_in[3];
    const float* fc1_W    = (const float*)d_in[4];
    const float* fc1_b    = (const float*)d_in[5];
    const float* attn_Wq  = (const float*)d_in[6];
    const float* attn_bq  = (const float*)d_in[7];
    const float* attn_Wk  = (const float*)d_in[8];
    const float* attn_bk  = (const float*)d_in[9];
    const float* attn_v   = (const float*)d_in[10];
    const float* attn_bv  = (const float*)d_in[11];
    const float* fc0_W    = (const float*)d_in[12];
    const float* fc0_b    = (const float*)d_in[13];
    const float* Wi0      = (const float*)d_in[14];
    const float* Wh0      = (const float*)d_in[15];
    const float* bi0      = (const float*)d_in[16];
    const float* bh0      = (const float*)d_in[17];
    const float* WiL      = (const float*)d_in[18];
    const float* WhL      = (const float*)d_in[19];
    const float* biL      = (const float*)d_in[20];
    const float* bhL      = (const float*)d_in[21];
    const float* fc2_W    = (const float*)d_in[22];
    const float* fc2_b    = (const float*)d_in[23];
    float* out = (float*)d_out;

    float* sc = nullptr;
    cudaGetSymbolAddress((void**)&sc, g_scratch);
    float*  xemb   = sc + OFF_XEMB;
    __half* xseq16 = (__half*)(sc + OFF_XSEQ16);
    float*  giX    = sc + OFF_GIX;
    __half* keys16 = (__half*)(sc + OFF_KEYS16);
    __half* feat16 = (__half*)(sc + OFF_FEAT16);
    __half* Wq16   = (__half*)(sc + OFF_WQ16);
    __half* fc016  = (__half*)(sc + OFF_FC016);
    __half* fc216  = (__half*)(sc + OFF_FC216);
    __half* Wi0c   = (__half*)(sc + OFF_WI0C);
    __half* Wh016  = (__half*)(sc + OFF_WH016);
    __half* WiL16  = (__half*)(sc + OFF_WIL16);
    __half* WhL16  = (__half*)(sc + OFF_WHL16);
    float*  ebuf   = sc + OFF_E;
    float*  qp     = sc + OFF_QP;
    __half* ctx16  = (__half*)(sc + OFF_CTX16);
    __half* ctxH16 = (__half*)(sc + OFF_CTXH16);
    float*  h32A   = sc + OFF_H32A;
    float*  h32B   = sc + OFF_H32B;
    __half* h16A   = (__half*)(sc + OFF_H16A);
    __half* h16B   = (__half*)(sc + OFF_H16B);
    float*  fc0p   = sc + OFF_FC0P;
    __half* hAll16 = (__half*)(sc + OFF_HALL);
    __half* WkT16  = (__half*)(sc + OFF_WKT16);
    __half* Wi0x16 = (__half*)(sc + OFF_WI0X);
    __half* zero16 = h16A + 3 * CB * CH;

    zerok<<<1024, 256>>>(h32A, 4 * CB * CH);
    zerok<<<512, 256>>>((float*)h16A, 2 * CB * CH);
    gather_emb<<<CB * CT, 128>>>(emb, captions, sos, xemb);

    // fp16 conversions / transposes
    transpose_h<<<dim3(32, 32), dim3(32, 8)>>>(attn_Wq, Wq16, CH, CH);
    transpose_h<<<dim3(32, 64), dim3(32, 8)>>>(fc0_W, fc016, CK, CH);
    transpose_h<<<dim3((CV + 31) / 32, 32), dim3(32, 8)>>>(fc2_W, fc216, CH, CV);
    transpose_h<<<dim3(32, 64), dim3(32, 8)>>>(attn_Wk, WkT16, CK, CH);
    conv_wi0half<<<(3072 * 512 + 255) / 256, 256>>>(Wi0, Wi0x16, 0);
    conv_wi0half<<<(3072 * 512 + 255) / 256, 256>>>(Wi0, Wi0c, 1024);
    conv_h<<<(3072 * 512 + 255) / 256, 256>>>(Wh0, Wh016, 3072 * 512);
    conv_h<<<(3 * 3072 * 512 + 255) / 256, 256>>>(WiL, WiL16, 3 * 3072 * 512);
    conv_h<<<(3 * 3072 * 512 + 255) / 256, 256>>>(WhL, WhL16, 3 * 3072 * 512);
    conv_h<<<(CB * CS * CK / 2 + 255) / 256, 256>>>(features, feat16, CB * CS * CK / 2);

    // xseq16[t*64+b][h] = half(xemb @ fc1_W + b)  (tf32, fp16 out)
    gemm_tf32<false, true><<<dim3(16, 8, 1), 256>>>(xemb, fc1_W, fc1_b, (float*)xseq16,
                                                    960, CE, CE, CH, CH, 0);
    // giX = Wi0[:, :1024] @ xseq^T  (fp16 GEMM, fp32 out [3072][960])
    gemm_h<false, false><<<dim3(15, 24, 1), 256>>>(Wi0x16, xseq16, nullptr, giX,
                                                   3 * CH, CH, CH, CH, 960, 0);
    // keys16 = half(features @ attn_Wk + bk)  (fp16 GEMM)
    gemm_h<false, true><<<dim3(16, 98, 1), 256>>>(feat16, WkT16, attn_bk, (float*)keys16,
                                                  CB * CS, CK, CK, CK, CH, 0);

    for (int t = 0; t < CT; t++) {
        float*  cur32 = (t & 1) ? h32B : h32A;
        float*  nxt32 = (t & 1) ? h32A : h32B;
        __half* cur16 = (t & 1) ? h16B : h16A;
        __half* nxt16 = (t & 1) ? h16A : h16B;
        const __half* htop16 = (t == 0) ? zero16 : hAll16 + (size_t)(t - 1) * CB * CH;

        gemm_h<true, false><<<dim3(1, 8, 8), 256>>>(Wq16, htop16, nullptr, qp,
                                                    CH, CH, CH, CH, CH, (size_t)CB * CH);
        e2_kernel<<<dim3(4, CB), 256>>>(qp, attn_bq, keys16, attn_v, attn_bv, ebuf);
        ctxsm_h<<<dim3(32, 8), 256>>>(ebuf, feat16, ctx16);
        gemm_h<false, false><<<dim3(1, 8, 8), 256>>>(fc016, ctx16, nullptr, fc0p,
                                                     CH, CK, CK, CK, 64, (size_t)CB * CH);
        reduce64h<<<256, 256>>>(fc0p, fc0_b, ctxH16, 8, (size_t)CB * CH);

        gru_h<<<64, 192>>>(Wi0c, Wh016, ctxH16, cur16, cur32, nxt32, nxt16,
                           giX + t * 64, bi0, bh0);
        for (int l = 1; l < 3; l++) {
            gru_h<<<64, 192>>>(WiL16 + (size_t)(l - 1) * 3 * CH * CH,
                               WhL16 + (size_t)(l - 1) * 3 * CH * CH,
                               nxt16 + (size_t)(l - 1) * CB * CH,
                               cur16 + (size_t)l * CB * CH,
                               cur32 + (size_t)l * CB * CH,
                               nxt32 + (size_t)l * CB * CH,
                               nxt16 + (size_t)l * CB * CH,
                               nullptr,
                               biL + (size_t)(l - 1) * 3 * CH,
                               bhL + (size_t)(l - 1) * 3 * CH);
        }
        gru_h<<<64, 192>>>(WiL16 + (size_t)2 * 3 * CH * CH,
                           WhL16 + (size_t)2 * 3 * CH * CH,
                           nxt16 + (size_t)2 * CB * CH,
                           htop16,
                           cur32 + (size_t)3 * CB * CH,
                           nxt32 + (size_t)3 * CB * CH,
                           hAll16 + (size_t)t * CB * CH,
                           nullptr,
                           biL + (size_t)2 * 3 * CH,
                           bhL + (size_t)2 * 3 * CH);
    }

    gemm_fc2_final<<<dim3(15, 79), 256>>>(fc216, hAll16, fc2_b, out, CV);
}